// round 4
// baseline (speedup 1.0000x reference)
#include <cuda_runtime.h>
#include <math.h>

#define BB 32
#define PP 64
#define LL 64
#define VV 32000

// Scratch (no allocations allowed). Zero-initialized at module load;
// g_flag/g_done are reset to 0 by the last block each replay.
__device__ uint2    g_mask[BB * PP];   // truth bitmask per (b,i)
__device__ int      g_flag[BB];        // DP-done flag per batch
__device__ double   g_klrow[BB * PP];  // per-(b,i) KL value (plain stores)
__device__ unsigned g_done;            // block completion counter

// ---------------------------------------------------------------------------
// Single fused kernel: one block per (b,i) row of outputs (grid = 2048).
//   blocks 0..31 : warp 0 first runs the edit-distance DP for batch blockIdx.x
//                  (registers + shuffles only), publishes g_mask + g_flag.
//   all blocks   : stream-sum their 128KB outputs row (HBM-bound), wait on
//                  flag[b], dedup-gather distinct argmin symbols (L2-hot),
//                  compute analytic KL in double, plain-store to g_klrow.
//   last block   : fence+counter; reduces g_klrow (L2-hot), writes scalar,
//                  resets g_flag / g_done for the next graph replay.
//
// Analytic collapse of softmax+KL: q has 2 levels -> p1=e/D, p0=1/D with
// D=(V-m)+m*e, m=#distinct argmin target symbols. ln p1=1-lnD, ln p0=-lnD.
// kl = m*p1*(1-lnD) - (V-m)*p0*lnD - p0*sumAll - (p1-p0)*Ssum
// ---------------------------------------------------------------------------
__global__ void __launch_bounds__(256) k_main(const float* __restrict__ outputs,
                                              const int* __restrict__ syms,
                                              const int* __restrict__ targets,
                                              const unsigned char* __restrict__ mask,
                                              float* __restrict__ out) {
    const unsigned FULL = 0xffffffffu;
    int bp    = blockIdx.x;          // 0..2047
    int b     = bp >> 6;
    int i_row = bp & 63;
    int tid   = threadIdx.x;
    int lane  = tid & 31, wid = tid >> 5;

    // ---------------- DP (blocks 0..31, warp 0 only) ----------------
    if (bp < BB && wid == 0) {
        int bd = bp;
        int j0 = 2 * lane, j1 = 2 * lane + 1;
        int tg0 = targets[bd * LL + j0];
        int tg1 = targets[bd * LL + j1];
        int mk0 = mask[bd * LL + j0];
        int mk1 = mask[bd * LL + j1];
        int s0  = syms[bd * PP + j0];
        int s1  = syms[bd * PP + j1];
        int tgm1 = __shfl_up_sync(FULL, tg1, 1);   // tg[j0-1]
        float p0 = (float)j0, p1 = (float)j1;      // row 0 (exact ints in fp32)

        for (int i = 0; i < PP; i++) {
            float d0, d1;
            if (i == 0) {
                d0 = p0; d1 = p1;
            } else {
                int im1 = i - 1;
                int sym = __shfl_sync(FULL, (im1 & 1) ? s1 : s0, im1 >> 1);
                float p1m = __shfl_up_sync(FULL, p1, 1);    // prev[j0-1]
                float tmp0 = (lane == 0) ? (float)i
                           : fminf(p1m + ((sym != tgm1) ? 1.0f : 0.0f), p0 + 1.0f);
                float tmp1 = fminf(p0 + ((sym != tg0) ? 1.0f : 0.0f), p1 + 1.0f);
                float v0 = tmp0 - (float)j0;
                float sB = fminf(v0, tmp1 - (float)j1);     // pair-inclusive
                float sc = sB;
                #pragma unroll
                for (int off = 1; off < 32; off <<= 1) {
                    float o = __shfl_up_sync(FULL, sc, off);
                    if (lane >= off) sc = fminf(sc, o);
                }
                float e = __shfl_up_sync(FULL, sc, 1);      // exclusive prefix
                if (lane == 0) e = INFINITY;
                d0 = (float)j0 + fminf(e, v0);
                d1 = (float)j1 + fminf(e, sB);
                p0 = d0; p1 = d1;
            }
            float md0 = mk0 ? d0 : INFINITY;
            float md1 = mk1 ? d1 : INFINITY;
            float mv = fminf(md0, md1);
            #pragma unroll
            for (int off = 16; off; off >>= 1)
                mv = fminf(mv, __shfl_xor_sync(FULL, mv, off));
            unsigned mE = __ballot_sync(FULL, md0 == mv);
            unsigned mO = __ballot_sync(FULL, md1 == mv);
            if (lane == 0) g_mask[bd * PP + i] = make_uint2(mE, mO);
        }
        __threadfence();
        if (lane == 0) atomicExch(&g_flag[bd], 1);
    }

    // ---------------- rowsum (all blocks, HBM-bound) ----------------
    const float4* row4 = (const float4*)(outputs + (size_t)bp * VV);
    float acc = 0.0f;
    #pragma unroll 4
    for (int idx = tid; idx < VV / 4; idx += 256) {
        float4 v = row4[idx];
        acc += (v.x + v.y) + (v.z + v.w);
    }
    double dacc = (double)acc;
    #pragma unroll
    for (int off = 16; off; off >>= 1)
        dacc += __shfl_down_sync(FULL, dacc, off);
    __shared__ double sred[8];
    if (lane == 0) sred[wid] = dacc;

    // ---------------- wait for this batch's DP mask ----------------
    if (tid == 0) {
        while (atomicAdd(&g_flag[b], 0) == 0) __nanosleep(64);
    }
    __syncthreads();
    __threadfence();

    // ---------------- dedup gather of distinct argmin symbols ------
    __shared__ int stg[LL];
    __shared__ unsigned char str[LL];
    if (tid < LL) {
        stg[tid] = targets[b * LL + tid];
        uint2 m = g_mask[bp];
        str[tid] = (unsigned char)((((tid & 1) ? m.y : m.x) >> (tid >> 1)) & 1);
    }
    __syncthreads();

    float contrib = 0.0f, cm = 0.0f;
    if (tid < LL && str[tid]) {
        int tv = stg[tid];
        bool first = true;
        for (int k = 0; k < tid; k++)
            if (str[k] && stg[k] == tv) { first = false; break; }
        if (first) {
            contrib = outputs[(size_t)bp * VV + tv];   // L2-hot: row just streamed
            cm = 1.0f;
        }
    }
    #pragma unroll
    for (int off = 16; off; off >>= 1) {
        contrib += __shfl_down_sync(FULL, contrib, off);
        cm      += __shfl_down_sync(FULL, cm, off);
    }
    __shared__ float sc2[2], sm2[2];
    if (tid < LL && lane == 0) { sc2[wid] = contrib; sm2[wid] = cm; }
    __syncthreads();

    // ---------------- per-(b,i) KL (double), plain store ------------
    if (tid == 0) {
        double kl = 0.0;
        if (mask[b * LL + i_row]) {
            double sumAll = 0.0;
            #pragma unroll
            for (int w = 0; w < 8; w++) sumAll += sred[w];
            double Ssum = (double)(sc2[0] + sc2[1]);
            double m    = (double)(sm2[0] + sm2[1]);
            const double E1 = 2.718281828459045235360287;
            double D   = ((double)VV - m) + m * E1;
            double lnD = log(D);
            double p1  = E1 / D;
            double pz  = 1.0 / D;
            kl = m * p1 * (1.0 - lnD) - ((double)VV - m) * pz * lnD
               - pz * sumAll - (p1 - pz) * Ssum;
        }
        g_klrow[bp] = kl;
    }

    // ---------------- last-block final reduction --------------------
    __shared__ int s_last;
    if (tid == 0) {
        __threadfence();
        unsigned prev = atomicAdd(&g_done, 1u);
        s_last = (prev == (unsigned)(BB * PP - 1));
    }
    __syncthreads();
    if (!s_last) return;

    // All other blocks' g_klrow stores are visible (fence before counter).
    if (tid < BB) {
        int bb = tid;
        double s = 0.0;
        #pragma unroll 8
        for (int i = 0; i < PP; i++) s += g_klrow[bb * PP + i];
        float w = 0.0f;
        #pragma unroll
        for (int j = 0; j < LL; j++) w += (float)mask[bb * LL + j];
        double pb = s / ((double)w + 1e-13);
        double ne = (w > 0.0f) ? 1.0 : 0.0;
        #pragma unroll
        for (int off = 16; off; off >>= 1) {
            pb += __shfl_down_sync(FULL, pb, off);
            ne += __shfl_down_sync(FULL, ne, off);
        }
        if (tid == 0) out[0] = (float)(pb / (ne + 1e-13));
        // reset handshake state for next graph replay
        g_flag[bb] = 0;
        if (tid == 0) g_done = 0u;
    }
}

// ---------------------------------------------------------------------------
extern "C" void kernel_launch(void* const* d_in, const int* in_sizes, int n_in,
                              void* d_out, int out_size) {
    const float*         outputs = (const float*)d_in[0];
    const int*           syms    = (const int*)d_in[1];
    const int*           targets = (const int*)d_in[2];
    const unsigned char* mask    = (const unsigned char*)d_in[3];

    k_main<<<BB * PP, 256>>>(outputs, syms, targets, mask, (float*)d_out);
}